// round 8
// baseline (speedup 1.0000x reference)
#include <cuda_runtime.h>
#include <math.h>
#include <stdint.h>

#define SEQ   4096
#define CDIM  512
#define KDIM  256
#define VDIM  512
#define NH    8
#define DK    32
#define DV    64
#define BATCH 2

#define BM 128
#define BN 64

// Scratch (allocation-free per harness rules)
__device__ unsigned g_xh [BATCH * SEQ * 256];        // X^T split, [b][m][kp]
__device__ unsigned g_xl [BATCH * SEQ * 256];
__device__ unsigned g_wth[1536 * 256];               // W^T split, [n_glob][kp]
__device__ unsigned g_wtl[1536 * 256];               // (Wq|Wk|Wv|Wo)
__device__ unsigned g_qh [BATCH * SEQ * NH * 16];    // Q scaled split, [b][s][h][kp]
__device__ unsigned g_ql [BATCH * SEQ * NH * 16];
__device__ unsigned g_kh [BATCH * SEQ * NH * 16];
__device__ unsigned g_kl [BATCH * SEQ * NH * 16];
__device__ unsigned g_vth[BATCH * NH * DV * (SEQ/2)]; // V^T split, [b][h][vc][pair]
__device__ unsigned g_vtl[BATCH * NH * DV * (SEQ/2)];
__device__ unsigned g_aoh[BATCH * SEQ * 256];        // attn out split, [b][m][kp]
__device__ unsigned g_aol[BATCH * SEQ * 256];

// ---------------------------------------------------------------------------
// helpers
// ---------------------------------------------------------------------------
__device__ __forceinline__ void bsplit(float v0, float v1, unsigned& hi, unsigned& lo)
{
    asm("cvt.rn.bf16x2.f32 %0, %1, %2;" : "=r"(hi) : "f"(v1), "f"(v0));
    float h0 = __uint_as_float(hi << 16);
    float h1 = __uint_as_float(hi & 0xffff0000u);
    asm("cvt.rn.bf16x2.f32 %0, %1, %2;" : "=r"(lo) : "f"(v1 - h1), "f"(v0 - h0));
}

__device__ __forceinline__ void mma16(float c[4],
                                      unsigned a0, unsigned a1, unsigned a2, unsigned a3,
                                      unsigned b0, unsigned b1)
{
    asm volatile(
        "mma.sync.aligned.m16n8k16.row.col.f32.bf16.bf16.f32 "
        "{%0,%1,%2,%3},{%4,%5,%6,%7},{%8,%9},{%0,%1,%2,%3};"
        : "+f"(c[0]), "+f"(c[1]), "+f"(c[2]), "+f"(c[3])
        : "r"(a0), "r"(a1), "r"(a2), "r"(a3), "r"(b0), "r"(b1));
}

__device__ __forceinline__ unsigned sptr(const void* p) {
    return (unsigned)__cvta_generic_to_shared(p);
}

__device__ __forceinline__ void ldsm4(unsigned& r0, unsigned& r1,
                                      unsigned& r2, unsigned& r3, unsigned a)
{
    asm volatile("ldmatrix.sync.aligned.m8n8.x4.shared.b16 {%0,%1,%2,%3}, [%4];"
                 : "=r"(r0), "=r"(r1), "=r"(r2), "=r"(r3) : "r"(a));
}

__device__ __forceinline__ void cpa16(unsigned dst, const void* src) {
    asm volatile("cp.async.cg.shared.global [%0], [%1], 16;" :: "r"(dst), "l"(src));
}
#define CPA_COMMIT() asm volatile("cp.async.commit_group;")
#define CPA_WAIT(N)  asm volatile("cp.async.wait_group %0;" :: "n"(N))

#define AROW(l) (((l) & 7) + ((((l) >> 3) & 1) << 3))
#define ACOL(l) ((((l) >> 4) & 1) * 4)
#define BROW(l) (((l) & 7) + ((((l) >> 4) & 1) << 3))
#define BCOL(l) ((((l) >> 3) & 1) * 4)

// ---------------------------------------------------------------------------
// Kernel 0a: X^T presplit (transpose through SMEM).
// grid (SEQ/128, BATCH), 256 thr. Writes g_xh/g_xl [b][m][kp].
// ---------------------------------------------------------------------------
__global__ __launch_bounds__(256) void xsplit(const float* __restrict__ X)
{
    __shared__ float Xs[32][132];
    const int b  = blockIdx.y;
    const int m0 = blockIdx.x * 128;
    const int t  = threadIdx.x;
    const float* Xb = X + (size_t)b * CDIM * SEQ;

    for (int c0 = 0; c0 < CDIM; c0 += 32) {
        __syncthreads();
        #pragma unroll
        for (int i = t; i < 32 * 128; i += 256) {
            int cc = i >> 7, m = i & 127;
            Xs[cc][m] = Xb[(size_t)(c0 + cc) * SEQ + m0 + m];
        }
        __syncthreads();
        const int m    = t >> 1;
        const int kpi0 = (t & 1) * 8;
        unsigned hi[8], lo[8];
        #pragma unroll
        for (int j = 0; j < 8; j++) {
            int kl = kpi0 + j;
            bsplit(Xs[2 * kl][m], Xs[2 * kl + 1][m], hi[j], lo[j]);
        }
        size_t base = (size_t)(b * SEQ + m0 + m) * 256 + c0 / 2 + kpi0;
        *(uint4*)&g_xh[base]     = make_uint4(hi[0], hi[1], hi[2], hi[3]);
        *(uint4*)&g_xh[base + 4] = make_uint4(hi[4], hi[5], hi[6], hi[7]);
        *(uint4*)&g_xl[base]     = make_uint4(lo[0], lo[1], lo[2], lo[3]);
        *(uint4*)&g_xl[base + 4] = make_uint4(lo[4], lo[5], lo[6], lo[7]);
    }
}

// ---------------------------------------------------------------------------
// Kernel 0b: weight presplit (transposed). n_glob: 0-255 Wq, 256-511 Wk,
// 512-1023 Wv, 1024-1535 Wo. grid 24, 256 thr.
// ---------------------------------------------------------------------------
__global__ __launch_bounds__(256) void wsplit(
    const float* __restrict__ Wq, const float* __restrict__ Wk,
    const float* __restrict__ Wv, const float* __restrict__ Wo)
{
    const int t  = threadIdx.x;
    const int n  = blockIdx.x * 64 + (t >> 2);
    const int kq = (t & 3) * 64;

    const float* W; int ldw, col;
    if (n < 256)       { W = Wq; ldw = KDIM; col = n; }
    else if (n < 512)  { W = Wk; ldw = KDIM; col = n - 256; }
    else if (n < 1024) { W = Wv; ldw = VDIM; col = n - 512; }
    else               { W = Wo; ldw = CDIM; col = n - 1024; }

    for (int j = 0; j < 64; j++) {
        int kp = kq + j;
        unsigned hi, lo;
        bsplit(W[(size_t)(2 * kp) * ldw + col],
               W[(size_t)(2 * kp + 1) * ldw + col], hi, lo);
        g_wth[(size_t)n * 256 + kp] = hi;
        g_wtl[(size_t)n * 256 + kp] = lo;
    }
}

// ---------------------------------------------------------------------------
// Kernel 1: fused QKV projection, cp.async double-buffered, all presplit.
// ---------------------------------------------------------------------------
#define AP 20
#define WP 20
#define STG (2*128*AP + 2*64*WP)              // words per stage = 7680
#define GEMM_SMEM (2 * STG * 4)               // 61440 B

__global__ __launch_bounds__(256) void qkv_mma()
{
    extern __shared__ unsigned smg[];
    const unsigned smbase = sptr(smg);

    const int b  = blockIdx.z;
    const int m0 = blockIdx.x * 128;
    const int by = blockIdx.y;
    const int nglob0 = (by < 4) ? by * 64 : (by < 8) ? 256 + (by - 4) * 64
                                          : 512 + (by - 8) * 64;

    const int t    = threadIdx.x;
    const int w    = t >> 5;
    const int lane = t & 31;
    const int g    = lane >> 2;
    const int tg   = lane & 3;
    const int rA   = 16 * w + g;
    const int rB   = rA + 8;
    const size_t bm = (size_t)(b * SEQ + m0);

    #define QFILL(ki_, st_) {                                                   \
        unsigned ab = smbase + (unsigned)((st_) * STG) * 4;                     \
        _Pragma("unroll")                                                       \
        for (int i = t; i < 128 * 4; i += 256) {                                \
            int row = i >> 2, seg = (i & 3) * 4;                                \
            size_t src = (bm + row) * 256 + (ki_) * 16 + seg;                   \
            cpa16(ab + (unsigned)(row * AP + seg) * 4, g_xh + src);             \
            cpa16(ab + (unsigned)(128 * AP + row * AP + seg) * 4, g_xl + src);  \
        }                                                                       \
        unsigned wb = smbase + (unsigned)((st_) * STG + 2 * 128 * AP) * 4;      \
        { int row = t >> 2, seg = (t & 3) * 4;                                  \
          size_t src = (size_t)(nglob0 + row) * 256 + (ki_) * 16 + seg;         \
          cpa16(wb + (unsigned)(row * WP + seg) * 4, g_wth + src);              \
          cpa16(wb + (unsigned)(64 * WP + row * WP + seg) * 4, g_wtl + src); } }

    const unsigned aoff = (unsigned)((16 * w + AROW(lane)) * AP + ACOL(lane)) * 4;
    const unsigned boff = (unsigned)(BROW(lane) * WP + BCOL(lane)) * 4;

    float acc[8][4];
    #pragma unroll
    for (int n = 0; n < 8; n++)
        #pragma unroll
        for (int j = 0; j < 4; j++) acc[n][j] = 0.0f;

    QFILL(0, 0); CPA_COMMIT();

    for (int ki = 0; ki < 16; ki++) {
        const int st = ki & 1;
        __syncthreads();
        if (ki < 15) { QFILL(ki + 1, st ^ 1); CPA_COMMIT(); CPA_WAIT(1); }
        else         { CPA_WAIT(0); }
        __syncthreads();

        const unsigned aH = smbase + (unsigned)(st * STG) * 4 + aoff;
        const unsigned aL = aH + (unsigned)(128 * AP) * 4;
        const unsigned bH = smbase + (unsigned)(st * STG + 2 * 128 * AP) * 4 + boff;
        const unsigned bL = bH + (unsigned)(64 * WP) * 4;

        #pragma unroll
        for (int kc2 = 0; kc2 < 2; kc2++) {
            const unsigned ko = kc2 * 8 * 4;
            unsigned ah0, ah1, ah2, ah3, al0, al1, al2, al3;
            ldsm4(ah0, ah1, ah2, ah3, aH + ko);
            ldsm4(al0, al1, al2, al3, aL + ko);
            #pragma unroll
            for (int n2 = 0; n2 < 4; n2++) {
                const unsigned no = (unsigned)(n2 * 16 * WP) * 4 + ko;
                unsigned h0, h1, h2, h3, q0, q1, q2, q3;
                ldsm4(h0, h1, h2, h3, bH + no);
                ldsm4(q0, q1, q2, q3, bL + no);
                mma16(acc[2*n2],   ah0, ah1, ah2, ah3, h0, h1);
                mma16(acc[2*n2],   ah0, ah1, ah2, ah3, q0, q1);
                mma16(acc[2*n2],   al0, al1, al2, al3, h0, h1);
                mma16(acc[2*n2+1], ah0, ah1, ah2, ah3, h2, h3);
                mma16(acc[2*n2+1], ah0, ah1, ah2, ah3, q2, q3);
                mma16(acc[2*n2+1], al0, al1, al2, al3, h2, h3);
            }
        }
    }

    // ---- epilogue: write pre-split forms ----
    const int nbase = (by < 4) ? by * 64 : (by < 8) ? (by - 4) * 64 : (by - 8) * 64;
    if (by < 8) {
        const float scale = (by < 4) ? 0.17677669529663687f : 1.0f;
        unsigned* dsth = (by < 4) ? g_qh : g_kh;
        unsigned* dstl = (by < 4) ? g_ql : g_kl;
        #pragma unroll
        for (int n = 0; n < 8; n++) {
            int col = nbase + n * 8 + 2 * tg;
            int h   = col >> 5;
            int kp  = (col & 31) >> 1;
            unsigned hi, lo;
            bsplit(acc[n][0] * scale, acc[n][1] * scale, hi, lo);
            size_t iA = ((bm + rA) * NH + h) * 16 + kp;
            dsth[iA] = hi; dstl[iA] = lo;
            bsplit(acc[n][2] * scale, acc[n][3] * scale, hi, lo);
            size_t iB = ((bm + rB) * NH + h) * 16 + kp;
            dsth[iB] = hi; dstl[iB] = lo;
        }
    } else {
        const int h = by - 8;
        const int geven = (g & 1) == 0;
        const int prA = (m0 >> 1) + 8 * w + (g >> 1);
        const int prB = prA + 4;
        #pragma unroll
        for (int n = 0; n < 8; n++) {
            float o00 = acc[n][0], o01 = acc[n][1];
            float o10 = acc[n][2], o11 = acc[n][3];
            float q00 = __shfl_xor_sync(0xffffffffu, o00, 4);
            float q01 = __shfl_xor_sync(0xffffffffu, o01, 4);
            float q10 = __shfl_xor_sync(0xffffffffu, o10, 4);
            float q11 = __shfl_xor_sync(0xffffffffu, o11, 4);
            int   col = n * 8 + 2 * tg + (geven ? 0 : 1);
            float vA0 = geven ? o00 : q01;
            float vA1 = geven ? q00 : o01;
            float vB0 = geven ? o10 : q11;
            float vB1 = geven ? q10 : o11;
            size_t base = ((size_t)(b * NH + h) * DV + col) * (SEQ / 2);
            unsigned hi, lo;
            bsplit(vA0, vA1, hi, lo);
            g_vth[base + prA] = hi; g_vtl[base + prA] = lo;
            bsplit(vB0, vB1, hi, lo);
            g_vth[base + prB] = hi; g_vtl[base + prB] = lo;
        }
    }
}

// ---------------------------------------------------------------------------
// Kernel 2: causal flash attention (unchanged core; epilogue writes split AO).
// ---------------------------------------------------------------------------
#define QP 20
#define KP 20
#define VTP 36

#define SM_QH  0
#define SM_QL  (SM_QH + 128 * QP)
#define SM_K0  (SM_QL + 128 * QP)
#define SM_V0  (SM_K0 + 2 * 2 * 64 * KP)
#define ATTN_SMEM ((SM_V0 + 2 * 2 * 64 * VTP) * 4)   // 77824 B

__global__ __launch_bounds__(256, 2) void attn_kernel()
{
    extern __shared__ unsigned sma[];
    unsigned* Qh = sma + SM_QH;
    unsigned* Ql = sma + SM_QL;

    const int qb = gridDim.x - 1 - blockIdx.x;
    const int h  = blockIdx.y;
    const int b  = blockIdx.z;
    const int t  = threadIdx.x;
    const int w    = t >> 5;
    const int lane = t & 31;
    const int g    = lane >> 2;
    const int tg   = lane & 3;

    const int rA = 16 * w + g;
    const int rB = rA + 8;

    const unsigned* Kh_g = g_kh + ((size_t)b * SEQ * NH + h) * 16;
    const unsigned* Kl_g = g_kl + ((size_t)b * SEQ * NH + h) * 16;
    const unsigned* Vh_g = g_vth + (size_t)(b * NH + h) * DV * (SEQ / 2);
    const unsigned* Vl_g = g_vtl + (size_t)(b * NH + h) * DV * (SEQ / 2);

    const unsigned qw = (unsigned)((16 * w + AROW(lane)) * QP + ACOL(lane)) * 4;
    const unsigned kw = (unsigned)(BROW(lane) * KP + BCOL(lane)) * 4;
    const unsigned vw = (unsigned)(BROW(lane) * VTP + BCOL(lane)) * 4;
    const unsigned aQH = sptr(Qh) + qw, aQL = sptr(Ql) + qw;
    const unsigned kbuf0 = sptr(sma + SM_K0);
    const unsigned vbuf0 = sptr(sma + SM_V0);

    {
        const unsigned* Qh_g = g_qh + ((size_t)(b * SEQ + qb * BM) * NH + h) * 16;
        const unsigned* Ql_g = g_ql + ((size_t)(b * SEQ + qb * BM) * NH + h) * 16;
        #pragma unroll
        for (int i = t; i < 128 * 4; i += 256) {
            int row = i >> 2, seg = (i & 3) * 4;
            cpa16(sptr(Qh + row * QP + seg), Qh_g + (size_t)row * NH * 16 + seg);
            cpa16(sptr(Ql + row * QP + seg), Ql_g + (size_t)row * NH * 16 + seg);
        }
    }
    #define FILL_K(kb_, buf_)                                                   \
        { unsigned kb_base = kbuf0 + (unsigned)(buf_) * 2 * 64 * KP * 4;        \
          int i = t; { int row = i >> 2, seg = (i & 3) * 4;                     \
            size_t src = (size_t)((kb_) * BN + row) * NH * 16 + seg;            \
            cpa16(kb_base + (unsigned)(row * KP + seg) * 4, Kh_g + src);        \
            cpa16(kb_base + (unsigned)(64 * KP + row * KP + seg) * 4, Kl_g + src); } }
    #define FILL_V(kb_, buf_)                                                   \
        { unsigned vb_base = vbuf0 + (unsigned)(buf_) * 2 * 64 * VTP * 4;       \
          _Pragma("unroll")                                                     \
          for (int i = t; i < 64 * 8; i += 256) {                               \
            int vc = i >> 3, seg = (i & 7) * 4;                                 \
            size_t src = (size_t)vc * (SEQ / 2) + (kb_) * 32 + seg;             \
            cpa16(vb_base + (unsigned)(vc * VTP + seg) * 4, Vh_g + src);        \
            cpa16(vb_base + (unsigned)(64 * VTP + vc * VTP + seg) * 4, Vl_g + src); } }

    FILL_K(0, 0);
    FILL_V(0, 0);
    CPA_COMMIT();

    float m_i[2] = {-1e30f, -1e30f};
    float l_i[2] = {0.0f, 0.0f};
    float acc[8][4];
    #pragma unroll
    for (int n = 0; n < 8; n++)
        #pragma unroll
        for (int j = 0; j < 4; j++) acc[n][j] = 0.0f;

    const int kb_max = 2 * qb + 1;
    for (int kb = 0; kb <= kb_max; kb++) {
        const int buf = kb & 1;
        if (kb < kb_max) {
            FILL_K(kb + 1, buf ^ 1);
            FILL_V(kb + 1, buf ^ 1);
            CPA_COMMIT();
            CPA_WAIT(1);
        } else {
            CPA_WAIT(0);
        }
        __syncthreads();

        const unsigned aKH = kbuf0 + (unsigned)buf * 2 * 64 * KP * 4 + kw;
        const unsigned aKL = aKH + (unsigned)(64 * KP) * 4;
        const unsigned aVH = vbuf0 + (unsigned)buf * 2 * 64 * VTP * 4 + vw;
        const unsigned aVL = aVH + (unsigned)(64 * VTP) * 4;

        float s[8][4];
        #pragma unroll
        for (int n = 0; n < 8; n++)
            #pragma unroll
            for (int j = 0; j < 4; j++) s[n][j] = 0.0f;

        #pragma unroll
        for (int kc2 = 0; kc2 < 2; kc2++) {
            const unsigned ko = kc2 * 8 * 4;
            unsigned ah0, ah1, ah2, ah3, al0, al1, al2, al3;
            ldsm4(ah0, ah1, ah2, ah3, aQH + ko);
            ldsm4(al0, al1, al2, al3, aQL + ko);
            #pragma unroll
            for (int n2 = 0; n2 < 4; n2++) {
                const unsigned no = (unsigned)(n2 * 16 * KP) * 4 + ko;
                unsigned h0, h1, h2, h3, q0, q1, q2, q3;
                ldsm4(h0, h1, h2, h3, aKH + no);
                ldsm4(q0, q1, q2, q3, aKL + no);
                mma16(s[2*n2],   ah0, ah1, ah2, ah3, h0, h1);
                mma16(s[2*n2],   ah0, ah1, ah2, ah3, q0, q1);
                mma16(s[2*n2],   al0, al1, al2, al3, h0, h1);
                mma16(s[2*n2+1], ah0, ah1, ah2, ah3, h2, h3);
                mma16(s[2*n2+1], ah0, ah1, ah2, ah3, q2, q3);
                mma16(s[2*n2+1], al0, al1, al2, al3, h2, h3);
            }
        }

        if (kb >= 2 * qb) {
            const int rowA = qb * BM + rA;
            const int rowB = rowA + 8;
            #pragma unroll
            for (int n = 0; n < 8; n++) {
                int c = kb * BN + n * 8 + 2 * tg;
                if (c     > rowA) s[n][0] = -1e30f;
                if (c + 1 > rowA) s[n][1] = -1e30f;
                if (c     > rowB) s[n][2] = -1e30f;
                if (c + 1 > rowB) s[n][3] = -1e30f;
            }
        }

        unsigned pH[4][4], pL[4][4];
        #pragma unroll
        for (int half = 0; half < 2; half++) {
            const int j0 = half * 2;
            float mloc = s[0][j0];
            #pragma unroll
            for (int n = 0; n < 8; n++) {
                mloc = fmaxf(mloc, s[n][j0]);
                mloc = fmaxf(mloc, s[n][j0 + 1]);
            }
            mloc = fmaxf(mloc, __shfl_xor_sync(0xffffffffu, mloc, 1));
            mloc = fmaxf(mloc, __shfl_xor_sync(0xffffffffu, mloc, 2));

            float mn   = fmaxf(m_i[half], mloc);
            float corr = __expf(m_i[half] - mn);
            m_i[half] = mn;

            float ps = 0.0f;
            #pragma unroll
            for (int n = 0; n < 8; n++) {
                float p0 = __expf(s[n][j0]     - mn);
                float p1 = __expf(s[n][j0 + 1] - mn);
                ps += p0 + p1;
                unsigned hi, lo; bsplit(p0, p1, hi, lo);
                const int slot = (n & 1) * 2 + half;
                pH[n >> 1][slot] = hi;
                pL[n >> 1][slot] = lo;
            }
            ps += __shfl_xor_sync(0xffffffffu, ps, 1);
            ps += __shfl_xor_sync(0xffffffffu, ps, 2);

            l_i[half] = l_i[half] * corr + ps;
            #pragma unroll
            for (int n = 0; n < 8; n++) {
                acc[n][j0]     *= corr;
                acc[n][j0 + 1] *= corr;
            }
        }

        #pragma unroll
        for (int kc = 0; kc < 4; kc++) {
            const unsigned ko = kc * 8 * 4;
            #pragma unroll
            for (int n2 = 0; n2 < 4; n2++) {
                const unsigned no = (unsigned)(n2 * 16 * VTP) * 4 + ko;
                unsigned h0, h1, h2, h3, q0, q1, q2, q3;
                ldsm4(h0, h1, h2, h3, aVH + no);
                ldsm4(q0, q1, q2, q3, aVL + no);
                mma16(acc[2*n2],   pH[kc][0], pH[kc][1], pH[kc][2], pH[kc][3], h0, h1);
                mma16(acc[2*n2],   pL[kc][0], pL[kc][1], pL[kc][2], pL[kc][3], h0, h1);
                mma16(acc[2*n2],   pH[kc][0], pH[kc][1], pH[kc][2], pH[kc][3], q0, q1);
                mma16(acc[2*n2+1], pH[kc][0], pH[kc][1], pH[kc][2], pH[kc][3], h2, h3);
                mma16(acc[2*n2+1], pL[kc][0], pL[kc][1], pL[kc][2], pL[kc][3], h2, h3);
                mma16(acc[2*n2+1], pH[kc][0], pH[kc][1], pH[kc][2], pH[kc][3], q2, q3);
            }
        }
        __syncthreads();
    }

    // ---- epilogue: write pre-split AO ----
    float inv0 = 1.0f / l_i[0];
    float inv1 = 1.0f / l_i[1];
    const size_t rbase = (size_t)(b * SEQ + qb * BM);
    #pragma unroll
    for (int n = 0; n < 8; n++) {
        int pg = h * 32 + n * 4 + tg;
        unsigned hi, lo;
        bsplit(acc[n][0] * inv0, acc[n][1] * inv0, hi, lo);
        g_aoh[(rbase + rA) * 256 + pg] = hi;
        g_aol[(rbase + rA) * 256 + pg] = lo;
        bsplit(acc[n][2] * inv1, acc[n][3] * inv1, hi, lo);
        g_aoh[(rbase + rB) * 256 + pg] = hi;
        g_aol[(rbase + rB) * 256 + pg] = lo;
    }
}

// ---------------------------------------------------------------------------
// Kernel 3: output projection, cp.async double-buffered, all presplit.
// ---------------------------------------------------------------------------
__global__ __launch_bounds__(256) void out_mma(float* __restrict__ out)
{
    extern __shared__ unsigned smo[];
    const unsigned smbase = sptr(smo);

    const int b  = blockIdx.z;
    const int m0 = blockIdx.x * 128;
    const int n0 = blockIdx.y * 64;
    const int nglob0 = 1024 + n0;

    float* C = out + (size_t)b * SEQ * CDIM;
    const int t    = threadIdx.x;
    const int w    = t >> 5;
    const int lane = t & 31;
    const int g    = lane >> 2;
    const int tg   = lane & 3;
    const int rA   = 16 * w + g;
    const int rB   = rA + 8;
    const size_t bm = (size_t)(b * SEQ + m0);

    #define OFILL(ki_, st_) {                                                   \
        unsigned ab = smbase + (unsigned)((st_) * STG) * 4;                     \
        _Pragma("unroll")                                                       \
        for (int i = t; i < 128 * 4; i += 256) {                                \
            int row = i >> 2, seg = (i & 3) * 4;                                \
            size_t src = (bm + row) * 256 + (ki_) * 16 + seg;                   \
            cpa16(ab + (unsigned)(row * AP + seg) * 4, g_aoh + src);            \
            cpa16(ab + (unsigned)(128 * AP + row * AP + seg) * 4, g_aol + src); \
        }                                                                       \
        unsigned wb = smbase + (unsigned)((st_) * STG + 2 * 128 * AP) * 4;      \
        { int row = t >> 2, seg = (t & 3) * 4;                                  \
          size_t src = (size_t)(nglob0 + row) * 256 + (ki_) * 16 + seg;         \
          cpa16(wb + (unsigned)(row * WP + seg) * 4, g_wth + src);              \
          cpa16(wb + (unsigned)(64 * WP + row * WP + seg) * 4, g_wtl + src); } }

    const unsigned aoff = (unsigned)((16 * w + AROW(lane)) * AP + ACOL(lane)) * 4;
    const unsigned boff = (unsigned)(BROW(lane) * WP + BCOL(lane)) * 4;

    float acc[8][4];
    #pragma unroll
    for (int n = 0; n < 8; n++)
        #pragma unroll
        for (int j = 0; j < 4; j++) acc[n][j] = 0.0f;

    OFILL(0, 0); CPA_COMMIT();

    for (int ki = 0; ki < 16; ki++) {
        const int st = ki & 1;
        __syncthreads();
        if (ki < 15) { OFILL(ki + 1, st ^ 1); CPA_COMMIT(); CPA_WAIT(1); }
        else         { CPA_WAIT(0); }
        __syncthreads();

        const unsigned aH = smbase + (unsigned)(st * STG) * 4 + aoff;
        const unsigned aL = aH + (unsigned)(128 * AP) * 4;
        const unsigned bH = smbase + (unsigned)(st * STG + 2 * 128 * AP) * 4 + boff;
        const unsigned bL = bH + (unsigned)(64 * WP) * 4;

        #pragma unroll
        for (int kc2 = 0; kc2 < 2; kc2++) {
            const unsigned ko = kc2 * 8 * 4;
            unsigned ah0, ah1, ah2, ah3, al0, al1, al2, al3;
            ldsm4(ah0, ah1, ah2, ah3, aH + ko);
            ldsm4(al0, al1, al2, al3, aL + ko);
            #pragma unroll
            for (int n2 = 0; n2 < 4; n2++) {
                const unsigned no = (unsigned)(n2 * 16 * WP) * 4 + ko;
                unsigned h0, h1, h2, h3, q0, q1, q2, q3;
                ldsm4(h0, h1, h2, h3, bH + no);
                ldsm4(q0, q1, q2, q3, bL + no);
                mma16(acc[2*n2],   ah0, ah1, ah2, ah3, h0, h1);
                mma16(acc[2*n2],   ah0, ah1, ah2, ah3, q0, q1);
                mma16(acc[2*n2],   al0, al1, al2, al3, h0, h1);
                mma16(acc[2*n2+1], ah0, ah1, ah2, ah3, h2, h3);
                mma16(acc[2*n2+1], ah0, ah1, ah2, ah3, q2, q3);
                mma16(acc[2*n2+1], al0, al1, al2, al3, h2, h3);
            }
        }
    }

    #pragma unroll
    for (int n = 0; n < 8; n++) {
        float2 o0, o1;
        o0.x = acc[n][0]; o0.y = acc[n][1];
        o1.x = acc[n][2]; o1.y = acc[n][3];
        *(float2*)&C[(size_t)(m0 + rA) * CDIM + n0 + n * 8 + 2 * tg] = o0;
        *(float2*)&C[(size_t)(m0 + rB) * CDIM + n0 + n * 8 + 2 * tg] = o1;
    }
}

extern "C" void kernel_launch(void* const* d_in, const int* in_sizes, int n_in,
                              void* d_out, int out_size)
{
    const float* X  = (const float*)d_in[0];
    const float* Wq = (const float*)d_in[1];
    const float* Wk = (const float*)d_in[2];
    const float* Wv = (const float*)d_in[3];
    const float* Wo = (const float*)d_in[4];
    float* out = (float*)d_out;

    cudaFuncSetAttribute(qkv_mma,
                         cudaFuncAttributeMaxDynamicSharedMemorySize, GEMM_SMEM);
    cudaFuncSetAttribute(out_mma,
                         cudaFuncAttributeMaxDynamicSharedMemorySize, GEMM_SMEM);
    cudaFuncSetAttribute(attn_kernel,
                         cudaFuncAttributeMaxDynamicSharedMemorySize, ATTN_SMEM);

    xsplit<<<dim3(SEQ / 128, BATCH), 256>>>(X);
    wsplit<<<24, 256>>>(Wq, Wk, Wv, Wo);

    dim3 g1(SEQ / 128, 16, BATCH);
    qkv_mma<<<g1, 256, GEMM_SMEM>>>();

    dim3 g2(SEQ / BM, NH, BATCH);
    attn_kernel<<<g2, 256, ATTN_SMEM>>>();

    dim3 g3(SEQ / 128, CDIM / 64, BATCH);
    out_mma<<<g3, 256, GEMM_SMEM>>>(out);
}

// round 10
// speedup vs baseline: 1.3423x; 1.3423x over previous
#include <cuda_runtime.h>
#include <math.h>
#include <stdint.h>

#define SEQ   4096
#define CDIM  512
#define KDIM  256
#define VDIM  512
#define NH    8
#define DK    32
#define DV    64
#define BATCH 2

#define BM 128
#define BN 64

// Scratch (allocation-free per harness rules)
__device__ unsigned g_qh[BATCH * SEQ * NH * 16];   // Q (scaled*log2e) split hi, [b][s][h][kp]
__device__ unsigned g_ql[BATCH * SEQ * NH * 16];
__device__ unsigned g_kh[BATCH * SEQ * NH * 16];
__device__ unsigned g_kl[BATCH * SEQ * NH * 16];
__device__ unsigned g_vt[BATCH * NH * DV * (SEQ / 2)];  // V^T fp16x2, [b][h][vc][pair]
__device__ float    g_ao[BATCH * SEQ * VDIM];

// ---------------------------------------------------------------------------
// helpers
// ---------------------------------------------------------------------------
__device__ __forceinline__ void bsplit(float v0, float v1, unsigned& hi, unsigned& lo)
{
    asm("cvt.rn.bf16x2.f32 %0, %1, %2;" : "=r"(hi) : "f"(v1), "f"(v0));
    float h0 = __uint_as_float(hi << 16);
    float h1 = __uint_as_float(hi & 0xffff0000u);
    asm("cvt.rn.bf16x2.f32 %0, %1, %2;" : "=r"(lo) : "f"(v1 - h1), "f"(v0 - h0));
}

__device__ __forceinline__ unsigned f16pack(float v0, float v1)
{
    unsigned r;
    asm("cvt.rn.f16x2.f32 %0, %1, %2;" : "=r"(r) : "f"(v1), "f"(v0));
    return r;
}

__device__ __forceinline__ float ex2(float x)
{
    float r;
    asm("ex2.approx.f32 %0, %1;" : "=f"(r) : "f"(x));
    return r;
}

__device__ __forceinline__ void mma16(float c[4],
                                      unsigned a0, unsigned a1, unsigned a2, unsigned a3,
                                      unsigned b0, unsigned b1)
{
    asm volatile(
        "mma.sync.aligned.m16n8k16.row.col.f32.bf16.bf16.f32 "
        "{%0,%1,%2,%3},{%4,%5,%6,%7},{%8,%9},{%0,%1,%2,%3};"
        : "+f"(c[0]), "+f"(c[1]), "+f"(c[2]), "+f"(c[3])
        : "r"(a0), "r"(a1), "r"(a2), "r"(a3), "r"(b0), "r"(b1));
}

__device__ __forceinline__ void mma16h(float c[4],
                                       unsigned a0, unsigned a1, unsigned a2, unsigned a3,
                                       unsigned b0, unsigned b1)
{
    asm volatile(
        "mma.sync.aligned.m16n8k16.row.col.f32.f16.f16.f32 "
        "{%0,%1,%2,%3},{%4,%5,%6,%7},{%8,%9},{%0,%1,%2,%3};"
        : "+f"(c[0]), "+f"(c[1]), "+f"(c[2]), "+f"(c[3])
        : "r"(a0), "r"(a1), "r"(a2), "r"(a3), "r"(b0), "r"(b1));
}

__device__ __forceinline__ unsigned sptr(const void* p) {
    return (unsigned)__cvta_generic_to_shared(p);
}

__device__ __forceinline__ void ldsm4(unsigned& r0, unsigned& r1,
                                      unsigned& r2, unsigned& r3, unsigned a)
{
    asm volatile("ldmatrix.sync.aligned.m8n8.x4.shared.b16 {%0,%1,%2,%3}, [%4];"
                 : "=r"(r0), "=r"(r1), "=r"(r2), "=r"(r3) : "r"(a));
}

__device__ __forceinline__ void cpa16(unsigned dst, const void* src) {
    asm volatile("cp.async.cg.shared.global [%0], [%1], 16;" :: "r"(dst), "l"(src));
}
#define CPA_COMMIT() asm volatile("cp.async.commit_group;")
#define CPA_WAIT(N)  asm volatile("cp.async.wait_group %0;" :: "n"(N))

#define AROW(l) (((l) & 7) + ((((l) >> 3) & 1) << 3))
#define ACOL(l) ((((l) >> 4) & 1) * 4)
#define BROW(l) (((l) & 7) + ((((l) >> 4) & 1) << 3))
#define BCOL(l) ((((l) >> 3) & 1) * 4)

// ---------------------------------------------------------------------------
// Kernel 1: fused QKV projection, bf16 mma + ldmatrix; epilogue writes
// pre-split bf16 Q/K (Q scaled by log2e/sqrt(dk)) and fp16 V^T.
// ---------------------------------------------------------------------------
#define AP 20
#define WP 20
#define QKV_SMEM ((2*128*AP + 2*64*WP) * 4)   // 30720 B

__global__ __launch_bounds__(256) void qkv_mma(
    const float* __restrict__ X,
    const float* __restrict__ Wq,
    const float* __restrict__ Wk,
    const float* __restrict__ Wv)
{
    extern __shared__ unsigned smg[];
    unsigned* Ah  = smg;
    unsigned* Al  = Ah  + 128 * AP;
    unsigned* Wth = Al  + 128 * AP;
    unsigned* Wtl = Wth + 64 * WP;

    const int b  = blockIdx.z;
    const int m0 = blockIdx.x * 128;
    const int by = blockIdx.y;

    const float* Wpt; int nbase, ldw;
    if (by < 4)      { Wpt = Wq; nbase = by * 64;       ldw = KDIM; }
    else if (by < 8) { Wpt = Wk; nbase = (by - 4) * 64; ldw = KDIM; }
    else             { Wpt = Wv; nbase = (by - 8) * 64; ldw = VDIM; }

    const float* A = X + (size_t)b * CDIM * SEQ;
    const int t    = threadIdx.x;
    const int w    = t >> 5;
    const int lane = t & 31;
    const int g    = lane >> 2;
    const int tg   = lane & 3;
    const int rA   = 16 * w + g;
    const int rB   = rA + 8;

    const unsigned aw = (unsigned)((16 * w + AROW(lane)) * AP + ACOL(lane)) * 4;
    const unsigned bw = (unsigned)(BROW(lane) * WP + BCOL(lane)) * 4;
    const unsigned aH = sptr(Ah) + aw,  aL = sptr(Al) + aw;
    const unsigned bH = sptr(Wth) + bw, bL = sptr(Wtl) + bw;

    float acc[8][4];
    #pragma unroll
    for (int n = 0; n < 8; n++)
        #pragma unroll
        for (int j = 0; j < 4; j++) acc[n][j] = 0.0f;

    for (int k0 = 0; k0 < CDIM; k0 += 32) {
        __syncthreads();
        #pragma unroll
        for (int i = t; i < 128 * 16; i += 256) {
            int m = i & 127, kp = i >> 7;
            float v0 = A[(size_t)(k0 + 2 * kp)     * SEQ + m0 + m];
            float v1 = A[(size_t)(k0 + 2 * kp + 1) * SEQ + m0 + m];
            unsigned hi, lo; bsplit(v0, v1, hi, lo);
            Ah[m * AP + kp] = hi; Al[m * AP + kp] = lo;
        }
        #pragma unroll
        for (int i = t; i < 64 * 16; i += 256) {
            int n = i & 63, kp = i >> 6;
            float v0 = Wpt[(size_t)(k0 + 2 * kp)     * ldw + nbase + n];
            float v1 = Wpt[(size_t)(k0 + 2 * kp + 1) * ldw + nbase + n];
            unsigned hi, lo; bsplit(v0, v1, hi, lo);
            Wth[n * WP + kp] = hi; Wtl[n * WP + kp] = lo;
        }
        __syncthreads();

        #pragma unroll
        for (int kc2 = 0; kc2 < 2; kc2++) {
            const unsigned ko = kc2 * 8 * 4;
            unsigned ah0, ah1, ah2, ah3, al0, al1, al2, al3;
            ldsm4(ah0, ah1, ah2, ah3, aH + ko);
            ldsm4(al0, al1, al2, al3, aL + ko);
            #pragma unroll
            for (int n2 = 0; n2 < 4; n2++) {
                const unsigned no = (unsigned)(n2 * 16 * WP) * 4 + ko;
                unsigned h0, h1, h2, h3, q0, q1, q2, q3;
                ldsm4(h0, h1, h2, h3, bH + no);
                ldsm4(q0, q1, q2, q3, bL + no);
                mma16(acc[2*n2],   ah0, ah1, ah2, ah3, h0, h1);
                mma16(acc[2*n2],   ah0, ah1, ah2, ah3, q0, q1);
                mma16(acc[2*n2],   al0, al1, al2, al3, h0, h1);
                mma16(acc[2*n2+1], ah0, ah1, ah2, ah3, h2, h3);
                mma16(acc[2*n2+1], ah0, ah1, ah2, ah3, q2, q3);
                mma16(acc[2*n2+1], al0, al1, al2, al3, h2, h3);
            }
        }
    }

    // ---- epilogue ----
    if (by < 8) {
        // Q: scaled by log2e/sqrt(32); K: unscaled. Both bf16 hi/lo, pairs along d.
        const float scale = (by < 4) ? 0.2550348757f : 1.0f;
        unsigned* dsth = (by < 4) ? g_qh : g_kh;
        unsigned* dstl = (by < 4) ? g_ql : g_kl;
        #pragma unroll
        for (int n = 0; n < 8; n++) {
            int col = nbase + n * 8 + 2 * tg;
            int h   = col >> 5;
            int kp  = (col & 31) >> 1;
            unsigned hi, lo;
            bsplit(acc[n][0] * scale, acc[n][1] * scale, hi, lo);
            size_t iA = ((size_t)(b * SEQ + m0 + rA) * NH + h) * 16 + kp;
            dsth[iA] = hi; dstl[iA] = lo;
            bsplit(acc[n][2] * scale, acc[n][3] * scale, hi, lo);
            size_t iB = ((size_t)(b * SEQ + m0 + rB) * NH + h) * 16 + kp;
            dsth[iB] = hi; dstl[iB] = lo;
        }
    } else {
        // V: transposed fp16, pairs along keys. Partner lane = lane^4.
        const int h = by - 8;
        const int geven = (g & 1) == 0;
        const int prA = (m0 >> 1) + 8 * w + (g >> 1);
        const int prB = prA + 4;
        #pragma unroll
        for (int n = 0; n < 8; n++) {
            float o00 = acc[n][0], o01 = acc[n][1];
            float o10 = acc[n][2], o11 = acc[n][3];
            float q00 = __shfl_xor_sync(0xffffffffu, o00, 4);
            float q01 = __shfl_xor_sync(0xffffffffu, o01, 4);
            float q10 = __shfl_xor_sync(0xffffffffu, o10, 4);
            float q11 = __shfl_xor_sync(0xffffffffu, o11, 4);
            int   col = n * 8 + 2 * tg + (geven ? 0 : 1);
            float vA0 = geven ? o00 : q01;
            float vA1 = geven ? q00 : o01;
            float vB0 = geven ? o10 : q11;
            float vB1 = geven ? q10 : o11;
            size_t base = ((size_t)(b * NH + h) * DV + col) * (SEQ / 2);
            g_vt[base + prA] = f16pack(vA0, vA1);
            g_vt[base + prB] = f16pack(vB0, vB1);
        }
    }
}

// ---------------------------------------------------------------------------
// Kernel 2: causal flash attention. QK bf16 3-term; PV fp16 single-term.
// cp.async double-buffered K/V; P register-resident fp16; base-2 softmax.
// ---------------------------------------------------------------------------
#define QP 20
#define KP 20
#define VTP 36

#define SM_QH  0
#define SM_QL  (SM_QH + 128 * QP)          // 2560
#define SM_K0  (SM_QL + 128 * QP)          // 5120 : K bufs, each 2*1280 (hi,lo)
#define SM_V0  (SM_K0 + 2 * 2 * 64 * KP)   // 10240 : V bufs, each 2304 (fp16)
#define ATTN_SMEM ((SM_V0 + 2 * 64 * VTP) * 4)   // 59392 B

__global__ __launch_bounds__(256, 2) void attn_kernel()
{
    extern __shared__ unsigned sma[];
    unsigned* Qh = sma + SM_QH;
    unsigned* Ql = sma + SM_QL;

    const int qb = gridDim.x - 1 - blockIdx.x;   // heavy blocks first
    const int h  = blockIdx.y;
    const int b  = blockIdx.z;
    const int t  = threadIdx.x;
    const int w    = t >> 5;
    const int lane = t & 31;
    const int g    = lane >> 2;
    const int tg   = lane & 3;

    const int rA = 16 * w + g;
    const int rB = rA + 8;

    const unsigned* Kh_g = g_kh + ((size_t)b * SEQ * NH + h) * 16;
    const unsigned* Kl_g = g_kl + ((size_t)b * SEQ * NH + h) * 16;
    const unsigned* V_g  = g_vt + (size_t)(b * NH + h) * DV * (SEQ / 2);

    const unsigned qw = (unsigned)((16 * w + AROW(lane)) * QP + ACOL(lane)) * 4;
    const unsigned kw = (unsigned)(BROW(lane) * KP + BCOL(lane)) * 4;
    const unsigned vw = (unsigned)(BROW(lane) * VTP + BCOL(lane)) * 4;
    const unsigned aQH = sptr(Qh) + qw, aQL = sptr(Ql) + qw;
    const unsigned kbuf0 = sptr(sma + SM_K0);
    const unsigned vbuf0 = sptr(sma + SM_V0);

    {
        const unsigned* Qh_g = g_qh + ((size_t)(b * SEQ + qb * BM) * NH + h) * 16;
        const unsigned* Ql_g = g_ql + ((size_t)(b * SEQ + qb * BM) * NH + h) * 16;
        #pragma unroll
        for (int i = t; i < 128 * 4; i += 256) {
            int row = i >> 2, seg = (i & 3) * 4;
            cpa16(sptr(Qh + row * QP + seg), Qh_g + (size_t)row * NH * 16 + seg);
            cpa16(sptr(Ql + row * QP + seg), Ql_g + (size_t)row * NH * 16 + seg);
        }
    }
    #define FILL_K(kb_, buf_)                                                   \
        { unsigned kb_base = kbuf0 + (unsigned)(buf_) * 2 * 64 * KP * 4;        \
          int i = t; { int row = i >> 2, seg = (i & 3) * 4;                     \
            size_t src = (size_t)((kb_) * BN + row) * NH * 16 + seg;            \
            cpa16(kb_base + (unsigned)(row * KP + seg) * 4, Kh_g + src);        \
            cpa16(kb_base + (unsigned)(64 * KP + row * KP + seg) * 4, Kl_g + src); } }
    #define FILL_V(kb_, buf_)                                                   \
        { unsigned vb_base = vbuf0 + (unsigned)(buf_) * 64 * VTP * 4;           \
          _Pragma("unroll")                                                     \
          for (int i = t; i < 64 * 8; i += 256) {                               \
            int vc = i >> 3, seg = (i & 7) * 4;                                 \
            size_t src = (size_t)vc * (SEQ / 2) + (kb_) * 32 + seg;             \
            cpa16(vb_base + (unsigned)(vc * VTP + seg) * 4, V_g + src); } }

    FILL_K(0, 0);
    FILL_V(0, 0);
    CPA_COMMIT();

    float m_i[2] = {-1e30f, -1e30f};
    float l_i[2] = {0.0f, 0.0f};
    float acc[8][4];
    #pragma unroll
    for (int n = 0; n < 8; n++)
        #pragma unroll
        for (int j = 0; j < 4; j++) acc[n][j] = 0.0f;

    const int kb_max = 2 * qb + 1;
    for (int kb = 0; kb <= kb_max; kb++) {
        const int buf = kb & 1;
        if (kb < kb_max) {
            FILL_K(kb + 1, buf ^ 1);
            FILL_V(kb + 1, buf ^ 1);
            CPA_COMMIT();
            CPA_WAIT(1);
        } else {
            CPA_WAIT(0);
        }
        __syncthreads();

        const unsigned aKH = kbuf0 + (unsigned)buf * 2 * 64 * KP * 4 + kw;
        const unsigned aKL = aKH + (unsigned)(64 * KP) * 4;
        const unsigned aV  = vbuf0 + (unsigned)buf * 64 * VTP * 4 + vw;

        // ---- QK (logits in base-2 units; log2e folded into Q)
        float s[8][4];
        #pragma unroll
        for (int n = 0; n < 8; n++)
            #pragma unroll
            for (int j = 0; j < 4; j++) s[n][j] = 0.0f;

        #pragma unroll
        for (int kc2 = 0; kc2 < 2; kc2++) {
            const unsigned ko = kc2 * 8 * 4;
            unsigned ah0, ah1, ah2, ah3, al0, al1, al2, al3;
            ldsm4(ah0, ah1, ah2, ah3, aQH + ko);
            ldsm4(al0, al1, al2, al3, aQL + ko);
            #pragma unroll
            for (int n2 = 0; n2 < 4; n2++) {
                const unsigned no = (unsigned)(n2 * 16 * KP) * 4 + ko;
                unsigned h0, h1, h2, h3, q0, q1, q2, q3;
                ldsm4(h0, h1, h2, h3, aKH + no);
                ldsm4(q0, q1, q2, q3, aKL + no);
                mma16(s[2*n2],   ah0, ah1, ah2, ah3, h0, h1);
                mma16(s[2*n2],   ah0, ah1, ah2, ah3, q0, q1);
                mma16(s[2*n2],   al0, al1, al2, al3, h0, h1);
                mma16(s[2*n2+1], ah0, ah1, ah2, ah3, h2, h3);
                mma16(s[2*n2+1], ah0, ah1, ah2, ah3, q2, q3);
                mma16(s[2*n2+1], al0, al1, al2, al3, h2, h3);
            }
        }

        // ---- causal mask
        if (kb >= 2 * qb) {
            const int rowA = qb * BM + rA;
            const int rowB = rowA + 8;
            #pragma unroll
            for (int n = 0; n < 8; n++) {
                int c = kb * BN + n * 8 + 2 * tg;
                if (c     > rowA) s[n][0] = -1e30f;
                if (c + 1 > rowA) s[n][1] = -1e30f;
                if (c     > rowB) s[n][2] = -1e30f;
                if (c + 1 > rowB) s[n][3] = -1e30f;
            }
        }

        // ---- online softmax (base-2); P packed fp16 into A-fragment regs
        unsigned pF[4][4];
        #pragma unroll
        for (int half = 0; half < 2; half++) {
            const int j0 = half * 2;
            float mloc = s[0][j0];
            #pragma unroll
            for (int n = 0; n < 8; n++) {
                mloc = fmaxf(mloc, s[n][j0]);
                mloc = fmaxf(mloc, s[n][j0 + 1]);
            }
            mloc = fmaxf(mloc, __shfl_xor_sync(0xffffffffu, mloc, 1));
            mloc = fmaxf(mloc, __shfl_xor_sync(0xffffffffu, mloc, 2));

            float mn   = fmaxf(m_i[half], mloc);
            float corr = ex2(m_i[half] - mn);
            m_i[half] = mn;

            float ps = 0.0f;
            #pragma unroll
            for (int n = 0; n < 8; n++) {
                float p0 = ex2(s[n][j0]     - mn);
                float p1 = ex2(s[n][j0 + 1] - mn);
                ps += p0 + p1;
                const int slot = (n & 1) * 2 + half;
                pF[n >> 1][slot] = f16pack(p0, p1);
            }
            ps += __shfl_xor_sync(0xffffffffu, ps, 1);
            ps += __shfl_xor_sync(0xffffffffu, ps, 2);

            l_i[half] = l_i[half] * corr + ps;
            #pragma unroll
            for (int n = 0; n < 8; n++) {
                acc[n][j0]     *= corr;
                acc[n][j0 + 1] *= corr;
            }
        }

        // ---- PV: single-term fp16
        #pragma unroll
        for (int kc = 0; kc < 4; kc++) {
            const unsigned ko = kc * 8 * 4;
            #pragma unroll
            for (int n2 = 0; n2 < 4; n2++) {
                const unsigned no = (unsigned)(n2 * 16 * VTP) * 4 + ko;
                unsigned v0, v1, v2, v3;
                ldsm4(v0, v1, v2, v3, aV + no);
                mma16h(acc[2*n2],   pF[kc][0], pF[kc][1], pF[kc][2], pF[kc][3], v0, v1);
                mma16h(acc[2*n2+1], pF[kc][0], pF[kc][1], pF[kc][2], pF[kc][3], v2, v3);
            }
        }
        __syncthreads();
    }

    // ---- epilogue
    float inv0 = 1.0f / l_i[0];
    float inv1 = 1.0f / l_i[1];
    float* Op = g_ao + ((size_t)b * SEQ + qb * BM) * VDIM + h * DV;
    #pragma unroll
    for (int n = 0; n < 8; n++) {
        float2 o0; o0.x = acc[n][0] * inv0; o0.y = acc[n][1] * inv0;
        float2 o1; o1.x = acc[n][2] * inv1; o1.y = acc[n][3] * inv1;
        *(float2*)&Op[(size_t)rA * VDIM + n * 8 + 2 * tg] = o0;
        *(float2*)&Op[(size_t)rB * VDIM + n * 8 + 2 * tg] = o1;
    }
}

// ---------------------------------------------------------------------------
// Kernel 3: output projection bf16 mma + ldmatrix (R7 version).
// ---------------------------------------------------------------------------
#define OUT_SMEM ((2*128*AP + 2*64*WP) * 4)

__global__ __launch_bounds__(256) void out_mma(
    const float* __restrict__ Wo, float* __restrict__ out)
{
    extern __shared__ unsigned smo[];
    unsigned* Ah  = smo;
    unsigned* Al  = Ah  + 128 * AP;
    unsigned* Wth = Al  + 128 * AP;
    unsigned* Wtl = Wth + 64 * WP;

    const int b  = blockIdx.z;
    const int m0 = blockIdx.x * 128;
    const int n0 = blockIdx.y * 64;

    const float* A = g_ao + (size_t)b * SEQ * VDIM;
    float* C = out + (size_t)b * SEQ * CDIM;

    const int t    = threadIdx.x;
    const int w    = t >> 5;
    const int lane = t & 31;
    const int g    = lane >> 2;
    const int tg   = lane & 3;
    const int rA   = 16 * w + g;
    const int rB   = rA + 8;

    const unsigned aw = (unsigned)((16 * w + AROW(lane)) * AP + ACOL(lane)) * 4;
    const unsigned bw = (unsigned)(BROW(lane) * WP + BCOL(lane)) * 4;
    const unsigned aH = sptr(Ah) + aw,  aL = sptr(Al) + aw;
    const unsigned bH = sptr(Wth) + bw, bL = sptr(Wtl) + bw;

    float acc[8][4];
    #pragma unroll
    for (int n = 0; n < 8; n++)
        #pragma unroll
        for (int j = 0; j < 4; j++) acc[n][j] = 0.0f;

    for (int k0 = 0; k0 < VDIM; k0 += 32) {
        __syncthreads();
        #pragma unroll
        for (int i = t; i < 128 * 16; i += 256) {
            int m = i >> 4, kp = i & 15;
            float2 v2 = *(const float2*)&A[(size_t)(m0 + m) * VDIM + k0 + 2 * kp];
            unsigned hi, lo; bsplit(v2.x, v2.y, hi, lo);
            Ah[m * AP + kp] = hi; Al[m * AP + kp] = lo;
        }
        #pragma unroll
        for (int i = t; i < 64 * 16; i += 256) {
            int n = i & 63, kp = i >> 6;
            float v0 = Wo[(size_t)(k0 + 2 * kp)     * CDIM + n0 + n];
            float v1 = Wo[(size_t)(k0 + 2 * kp + 1) * CDIM + n0 + n];
            unsigned hi, lo; bsplit(v0, v1, hi, lo);
            Wth[n * WP + kp] = hi; Wtl[n * WP + kp] = lo;
        }
        __syncthreads();

        #pragma unroll
        for (int kc2 = 0; kc2 < 2; kc2++) {
            const unsigned ko = kc2 * 8 * 4;
            unsigned ah0, ah1, ah2, ah3, al0, al1, al2, al3;
            ldsm4(ah0, ah1, ah2, ah3, aH + ko);
            ldsm4(al0, al1, al2, al3, aL + ko);
            #pragma unroll
            for (int n2 = 0; n2 < 4; n2++) {
                const unsigned no = (unsigned)(n2 * 16 * WP) * 4 + ko;
                unsigned h0, h1, h2, h3, q0, q1, q2, q3;
                ldsm4(h0, h1, h2, h3, bH + no);
                ldsm4(q0, q1, q2, q3, bL + no);
                mma16(acc[2*n2],   ah0, ah1, ah2, ah3, h0, h1);
                mma16(acc[2*n2],   ah0, ah1, ah2, ah3, q0, q1);
                mma16(acc[2*n2],   al0, al1, al2, al3, h0, h1);
                mma16(acc[2*n2+1], ah0, ah1, ah2, ah3, h2, h3);
                mma16(acc[2*n2+1], ah0, ah1, ah2, ah3, q2, q3);
                mma16(acc[2*n2+1], al0, al1, al2, al3, h2, h3);
            }
        }
    }

    #pragma unroll
    for (int n = 0; n < 8; n++) {
        float2 o0, o1;
        o0.x = acc[n][0]; o0.y = acc[n][1];
        o1.x = acc[n][2]; o1.y = acc[n][3];
        *(float2*)&C[(size_t)(m0 + rA) * CDIM + n0 + n * 8 + 2 * tg] = o0;
        *(float2*)&C[(size_t)(m0 + rB) * CDIM + n0 + n * 8 + 2 * tg] = o1;
    }
}

extern "C" void kernel_launch(void* const* d_in, const int* in_sizes, int n_in,
                              void* d_out, int out_size)
{
    const float* X  = (const float*)d_in[0];
    const float* Wq = (const float*)d_in[1];
    const float* Wk = (const float*)d_in[2];
    const float* Wv = (const float*)d_in[3];
    const float* Wo = (const float*)d_in[4];
    float* out = (float*)d_out;

    cudaFuncSetAttribute(attn_kernel,
                         cudaFuncAttributeMaxDynamicSharedMemorySize, ATTN_SMEM);

    dim3 g1(SEQ / 128, 16, BATCH);
    qkv_mma<<<g1, 256, QKV_SMEM>>>(X, Wq, Wk, Wv);

    dim3 g2(SEQ / BM, NH, BATCH);
    attn_kernel<<<g2, 256, ATTN_SMEM>>>();

    dim3 g3(SEQ / 128, CDIM / 64, BATCH);
    out_mma<<<g3, 256, OUT_SMEM>>>(Wo, out);
}

// round 11
// speedup vs baseline: 1.4684x; 1.0939x over previous
#include <cuda_runtime.h>
#include <math.h>
#include <stdint.h>

#define SEQ   4096
#define CDIM  512
#define KDIM  256
#define VDIM  512
#define NH    8
#define DK    32
#define DV    64
#define BATCH 2

#define BM 128
#define BN 64

// Scratch (allocation-free per harness rules)
__device__ unsigned g_qh[BATCH * SEQ * NH * 16];   // Q (scaled*log2e) split hi, [b][s][h][kp]
__device__ unsigned g_ql[BATCH * SEQ * NH * 16];
__device__ unsigned g_kh[BATCH * SEQ * NH * 16];
__device__ unsigned g_kl[BATCH * SEQ * NH * 16];
__device__ unsigned g_vt[BATCH * NH * DV * (SEQ / 2)];  // V^T fp16x2, [b][h][vc][pair]
__device__ float    g_ao[BATCH * SEQ * VDIM];

// ---------------------------------------------------------------------------
// helpers
// ---------------------------------------------------------------------------
__device__ __forceinline__ void bsplit(float v0, float v1, unsigned& hi, unsigned& lo)
{
    asm("cvt.rn.bf16x2.f32 %0, %1, %2;" : "=r"(hi) : "f"(v1), "f"(v0));
    float h0 = __uint_as_float(hi << 16);
    float h1 = __uint_as_float(hi & 0xffff0000u);
    asm("cvt.rn.bf16x2.f32 %0, %1, %2;" : "=r"(lo) : "f"(v1 - h1), "f"(v0 - h0));
}

__device__ __forceinline__ unsigned f16pack(float v0, float v1)
{
    unsigned r;
    asm("cvt.rn.f16x2.f32 %0, %1, %2;" : "=r"(r) : "f"(v1), "f"(v0));
    return r;
}

__device__ __forceinline__ float ex2(float x)
{
    float r;
    asm("ex2.approx.f32 %0, %1;" : "=f"(r) : "f"(x));
    return r;
}

__device__ __forceinline__ void mma16(float c[4],
                                      unsigned a0, unsigned a1, unsigned a2, unsigned a3,
                                      unsigned b0, unsigned b1)
{
    asm volatile(
        "mma.sync.aligned.m16n8k16.row.col.f32.bf16.bf16.f32 "
        "{%0,%1,%2,%3},{%4,%5,%6,%7},{%8,%9},{%0,%1,%2,%3};"
        : "+f"(c[0]), "+f"(c[1]), "+f"(c[2]), "+f"(c[3])
        : "r"(a0), "r"(a1), "r"(a2), "r"(a3), "r"(b0), "r"(b1));
}

__device__ __forceinline__ void mma16h(float c[4],
                                       unsigned a0, unsigned a1, unsigned a2, unsigned a3,
                                       unsigned b0, unsigned b1)
{
    asm volatile(
        "mma.sync.aligned.m16n8k16.row.col.f32.f16.f16.f32 "
        "{%0,%1,%2,%3},{%4,%5,%6,%7},{%8,%9},{%0,%1,%2,%3};"
        : "+f"(c[0]), "+f"(c[1]), "+f"(c[2]), "+f"(c[3])
        : "r"(a0), "r"(a1), "r"(a2), "r"(a3), "r"(b0), "r"(b1));
}

__device__ __forceinline__ unsigned sptr(const void* p) {
    return (unsigned)__cvta_generic_to_shared(p);
}

__device__ __forceinline__ void ldsm4(unsigned& r0, unsigned& r1,
                                      unsigned& r2, unsigned& r3, unsigned a)
{
    asm volatile("ldmatrix.sync.aligned.m8n8.x4.shared.b16 {%0,%1,%2,%3}, [%4];"
                 : "=r"(r0), "=r"(r1), "=r"(r2), "=r"(r3) : "r"(a));
}

__device__ __forceinline__ void cpa16(unsigned dst, const void* src) {
    asm volatile("cp.async.cg.shared.global [%0], [%1], 16;" :: "r"(dst), "l"(src));
}
#define CPA_COMMIT() asm volatile("cp.async.commit_group;")
#define CPA_WAIT(N)  asm volatile("cp.async.wait_group %0;" :: "n"(N))

#define AROW(l) (((l) & 7) + ((((l) >> 3) & 1) << 3))
#define ACOL(l) ((((l) >> 4) & 1) * 4)
#define BROW(l) (((l) & 7) + ((((l) >> 4) & 1) << 3))
#define BCOL(l) ((((l) >> 3) & 1) * 4)

// ---------------------------------------------------------------------------
// Kernel 1: fused QKV projection, N=128 per CTA (grid.y = 8).
// by 0-1: Q (scaled by log2e/sqrt32), 2-3: K, 4-7: V (2 heads per CTA).
// ---------------------------------------------------------------------------
#define AP 20
#define WP 20
#define QKV_SMEM ((2*128*AP + 2*128*WP) * 4)   // 40960 B

__global__ __launch_bounds__(256, 2) void qkv_mma(
    const float* __restrict__ X,
    const float* __restrict__ Wq,
    const float* __restrict__ Wk,
    const float* __restrict__ Wv)
{
    extern __shared__ unsigned smg[];
    unsigned* Ah  = smg;
    unsigned* Al  = Ah  + 128 * AP;
    unsigned* Wth = Al  + 128 * AP;
    unsigned* Wtl = Wth + 128 * WP;

    const int b  = blockIdx.z;
    const int m0 = blockIdx.x * 128;
    const int by = blockIdx.y;

    const float* Wpt; int nbase, ldw;
    if (by < 2)      { Wpt = Wq; nbase = by * 128;       ldw = KDIM; }
    else if (by < 4) { Wpt = Wk; nbase = (by - 2) * 128; ldw = KDIM; }
    else             { Wpt = Wv; nbase = (by - 4) * 128; ldw = VDIM; }

    const float* A = X + (size_t)b * CDIM * SEQ;
    const int t    = threadIdx.x;
    const int w    = t >> 5;
    const int lane = t & 31;
    const int g    = lane >> 2;
    const int tg   = lane & 3;
    const int rA   = 16 * w + g;
    const int rB   = rA + 8;

    const unsigned aw = (unsigned)((16 * w + AROW(lane)) * AP + ACOL(lane)) * 4;
    const unsigned bw = (unsigned)(BROW(lane) * WP + BCOL(lane)) * 4;
    const unsigned aH = sptr(Ah) + aw,  aL = sptr(Al) + aw;
    const unsigned bH = sptr(Wth) + bw, bL = sptr(Wtl) + bw;

    float acc[16][4];
    #pragma unroll
    for (int n = 0; n < 16; n++)
        #pragma unroll
        for (int j = 0; j < 4; j++) acc[n][j] = 0.0f;

    for (int k0 = 0; k0 < CDIM; k0 += 32) {
        __syncthreads();
        #pragma unroll
        for (int i = t; i < 128 * 16; i += 256) {
            int m = i & 127, kp = i >> 7;
            float v0 = A[(size_t)(k0 + 2 * kp)     * SEQ + m0 + m];
            float v1 = A[(size_t)(k0 + 2 * kp + 1) * SEQ + m0 + m];
            unsigned hi, lo; bsplit(v0, v1, hi, lo);
            Ah[m * AP + kp] = hi; Al[m * AP + kp] = lo;
        }
        #pragma unroll
        for (int i = t; i < 128 * 16; i += 256) {
            int n = i & 127, kp = i >> 7;
            float v0 = Wpt[(size_t)(k0 + 2 * kp)     * ldw + nbase + n];
            float v1 = Wpt[(size_t)(k0 + 2 * kp + 1) * ldw + nbase + n];
            unsigned hi, lo; bsplit(v0, v1, hi, lo);
            Wth[n * WP + kp] = hi; Wtl[n * WP + kp] = lo;
        }
        __syncthreads();

        #pragma unroll
        for (int kc2 = 0; kc2 < 2; kc2++) {
            const unsigned ko = kc2 * 8 * 4;
            unsigned ah0, ah1, ah2, ah3, al0, al1, al2, al3;
            ldsm4(ah0, ah1, ah2, ah3, aH + ko);
            ldsm4(al0, al1, al2, al3, aL + ko);
            #pragma unroll
            for (int n2 = 0; n2 < 8; n2++) {
                const unsigned no = (unsigned)(n2 * 16 * WP) * 4 + ko;
                unsigned h0, h1, h2, h3, q0, q1, q2, q3;
                ldsm4(h0, h1, h2, h3, bH + no);
                ldsm4(q0, q1, q2, q3, bL + no);
                mma16(acc[2*n2],   ah0, ah1, ah2, ah3, h0, h1);
                mma16(acc[2*n2],   ah0, ah1, ah2, ah3, q0, q1);
                mma16(acc[2*n2],   al0, al1, al2, al3, h0, h1);
                mma16(acc[2*n2+1], ah0, ah1, ah2, ah3, h2, h3);
                mma16(acc[2*n2+1], ah0, ah1, ah2, ah3, q2, q3);
                mma16(acc[2*n2+1], al0, al1, al2, al3, h2, h3);
            }
        }
    }

    // ---- epilogue ----
    if (by < 4) {
        // Q (scaled by log2e/sqrt32) or K: bf16 hi/lo, pairs along d.
        const float scale = (by < 2) ? 0.2550348757f : 1.0f;
        unsigned* dsth = (by < 2) ? g_qh : g_kh;
        unsigned* dstl = (by < 2) ? g_ql : g_kl;
        #pragma unroll
        for (int n = 0; n < 16; n++) {
            int col = nbase + n * 8 + 2 * tg;
            int h   = col >> 5;
            int kp  = (col & 31) >> 1;
            unsigned hi, lo;
            bsplit(acc[n][0] * scale, acc[n][1] * scale, hi, lo);
            size_t iA = ((size_t)(b * SEQ + m0 + rA) * NH + h) * 16 + kp;
            dsth[iA] = hi; dstl[iA] = lo;
            bsplit(acc[n][2] * scale, acc[n][3] * scale, hi, lo);
            size_t iB = ((size_t)(b * SEQ + m0 + rB) * NH + h) * 16 + kp;
            dsth[iB] = hi; dstl[iB] = lo;
        }
    } else {
        // V: transposed fp16, pairs along keys. Partner lane = lane^4.
        const int geven = (g & 1) == 0;
        const int prA = (m0 >> 1) + 8 * w + (g >> 1);
        const int prB = prA + 4;
        #pragma unroll
        for (int n = 0; n < 16; n++) {
            float o00 = acc[n][0], o01 = acc[n][1];
            float o10 = acc[n][2], o11 = acc[n][3];
            float q00 = __shfl_xor_sync(0xffffffffu, o00, 4);
            float q01 = __shfl_xor_sync(0xffffffffu, o01, 4);
            float q10 = __shfl_xor_sync(0xffffffffu, o10, 4);
            float q11 = __shfl_xor_sync(0xffffffffu, o11, 4);
            int   gv  = nbase + n * 8 + 2 * tg + (geven ? 0 : 1);
            int   h   = gv >> 6;
            int   vc  = gv & 63;
            float vA0 = geven ? o00 : q01;
            float vA1 = geven ? q00 : o01;
            float vB0 = geven ? o10 : q11;
            float vB1 = geven ? q10 : o11;
            size_t base = ((size_t)(b * NH + h) * DV + vc) * (SEQ / 2);
            g_vt[base + prA] = f16pack(vA0, vA1);
            g_vt[base + prB] = f16pack(vB0, vB1);
        }
    }
}

// ---------------------------------------------------------------------------
// Kernel 2: causal flash attention (unchanged from R10).
// ---------------------------------------------------------------------------
#define QP 20
#define KP 20
#define VTP 36

#define SM_QH  0
#define SM_QL  (SM_QH + 128 * QP)
#define SM_K0  (SM_QL + 128 * QP)
#define SM_V0  (SM_K0 + 2 * 2 * 64 * KP)
#define ATTN_SMEM ((SM_V0 + 2 * 64 * VTP) * 4)   // 59392 B

__global__ __launch_bounds__(256, 2) void attn_kernel()
{
    extern __shared__ unsigned sma[];
    unsigned* Qh = sma + SM_QH;
    unsigned* Ql = sma + SM_QL;

    const int qb = gridDim.x - 1 - blockIdx.x;
    const int h  = blockIdx.y;
    const int b  = blockIdx.z;
    const int t  = threadIdx.x;
    const int w    = t >> 5;
    const int lane = t & 31;
    const int g    = lane >> 2;
    const int tg   = lane & 3;

    const int rA = 16 * w + g;
    const int rB = rA + 8;

    const unsigned* Kh_g = g_kh + ((size_t)b * SEQ * NH + h) * 16;
    const unsigned* Kl_g = g_kl + ((size_t)b * SEQ * NH + h) * 16;
    const unsigned* V_g  = g_vt + (size_t)(b * NH + h) * DV * (SEQ / 2);

    const unsigned qw = (unsigned)((16 * w + AROW(lane)) * QP + ACOL(lane)) * 4;
    const unsigned kw = (unsigned)(BROW(lane) * KP + BCOL(lane)) * 4;
    const unsigned vw = (unsigned)(BROW(lane) * VTP + BCOL(lane)) * 4;
    const unsigned aQH = sptr(Qh) + qw, aQL = sptr(Ql) + qw;
    const unsigned kbuf0 = sptr(sma + SM_K0);
    const unsigned vbuf0 = sptr(sma + SM_V0);

    {
        const unsigned* Qh_g = g_qh + ((size_t)(b * SEQ + qb * BM) * NH + h) * 16;
        const unsigned* Ql_g = g_ql + ((size_t)(b * SEQ + qb * BM) * NH + h) * 16;
        #pragma unroll
        for (int i = t; i < 128 * 4; i += 256) {
            int row = i >> 2, seg = (i & 3) * 4;
            cpa16(sptr(Qh + row * QP + seg), Qh_g + (size_t)row * NH * 16 + seg);
            cpa16(sptr(Ql + row * QP + seg), Ql_g + (size_t)row * NH * 16 + seg);
        }
    }
    #define FILL_K(kb_, buf_)                                                   \
        { unsigned kb_base = kbuf0 + (unsigned)(buf_) * 2 * 64 * KP * 4;        \
          int i = t; { int row = i >> 2, seg = (i & 3) * 4;                     \
            size_t src = (size_t)((kb_) * BN + row) * NH * 16 + seg;            \
            cpa16(kb_base + (unsigned)(row * KP + seg) * 4, Kh_g + src);        \
            cpa16(kb_base + (unsigned)(64 * KP + row * KP + seg) * 4, Kl_g + src); } }
    #define FILL_V(kb_, buf_)                                                   \
        { unsigned vb_base = vbuf0 + (unsigned)(buf_) * 64 * VTP * 4;           \
          _Pragma("unroll")                                                     \
          for (int i = t; i < 64 * 8; i += 256) {                               \
            int vc = i >> 3, seg = (i & 7) * 4;                                 \
            size_t src = (size_t)vc * (SEQ / 2) + (kb_) * 32 + seg;             \
            cpa16(vb_base + (unsigned)(vc * VTP + seg) * 4, V_g + src); } }

    FILL_K(0, 0);
    FILL_V(0, 0);
    CPA_COMMIT();

    float m_i[2] = {-1e30f, -1e30f};
    float l_i[2] = {0.0f, 0.0f};
    float acc[8][4];
    #pragma unroll
    for (int n = 0; n < 8; n++)
        #pragma unroll
        for (int j = 0; j < 4; j++) acc[n][j] = 0.0f;

    const int kb_max = 2 * qb + 1;
    for (int kb = 0; kb <= kb_max; kb++) {
        const int buf = kb & 1;
        if (kb < kb_max) {
            FILL_K(kb + 1, buf ^ 1);
            FILL_V(kb + 1, buf ^ 1);
            CPA_COMMIT();
            CPA_WAIT(1);
        } else {
            CPA_WAIT(0);
        }
        __syncthreads();

        const unsigned aKH = kbuf0 + (unsigned)buf * 2 * 64 * KP * 4 + kw;
        const unsigned aKL = aKH + (unsigned)(64 * KP) * 4;
        const unsigned aV  = vbuf0 + (unsigned)buf * 64 * VTP * 4 + vw;

        float s[8][4];
        #pragma unroll
        for (int n = 0; n < 8; n++)
            #pragma unroll
            for (int j = 0; j < 4; j++) s[n][j] = 0.0f;

        #pragma unroll
        for (int kc2 = 0; kc2 < 2; kc2++) {
            const unsigned ko = kc2 * 8 * 4;
            unsigned ah0, ah1, ah2, ah3, al0, al1, al2, al3;
            ldsm4(ah0, ah1, ah2, ah3, aQH + ko);
            ldsm4(al0, al1, al2, al3, aQL + ko);
            #pragma unroll
            for (int n2 = 0; n2 < 4; n2++) {
                const unsigned no = (unsigned)(n2 * 16 * KP) * 4 + ko;
                unsigned h0, h1, h2, h3, q0, q1, q2, q3;
                ldsm4(h0, h1, h2, h3, aKH + no);
                ldsm4(q0, q1, q2, q3, aKL + no);
                mma16(s[2*n2],   ah0, ah1, ah2, ah3, h0, h1);
                mma16(s[2*n2],   ah0, ah1, ah2, ah3, q0, q1);
                mma16(s[2*n2],   al0, al1, al2, al3, h0, h1);
                mma16(s[2*n2+1], ah0, ah1, ah2, ah3, h2, h3);
                mma16(s[2*n2+1], ah0, ah1, ah2, ah3, q2, q3);
                mma16(s[2*n2+1], al0, al1, al2, al3, h2, h3);
            }
        }

        if (kb >= 2 * qb) {
            const int rowA = qb * BM + rA;
            const int rowB = rowA + 8;
            #pragma unroll
            for (int n = 0; n < 8; n++) {
                int c = kb * BN + n * 8 + 2 * tg;
                if (c     > rowA) s[n][0] = -1e30f;
                if (c + 1 > rowA) s[n][1] = -1e30f;
                if (c     > rowB) s[n][2] = -1e30f;
                if (c + 1 > rowB) s[n][3] = -1e30f;
            }
        }

        unsigned pF[4][4];
        #pragma unroll
        for (int half = 0; half < 2; half++) {
            const int j0 = half * 2;
            float mloc = s[0][j0];
            #pragma unroll
            for (int n = 0; n < 8; n++) {
                mloc = fmaxf(mloc, s[n][j0]);
                mloc = fmaxf(mloc, s[n][j0 + 1]);
            }
            mloc = fmaxf(mloc, __shfl_xor_sync(0xffffffffu, mloc, 1));
            mloc = fmaxf(mloc, __shfl_xor_sync(0xffffffffu, mloc, 2));

            float mn   = fmaxf(m_i[half], mloc);
            float corr = ex2(m_i[half] - mn);
            m_i[half] = mn;

            float ps = 0.0f;
            #pragma unroll
            for (int n = 0; n < 8; n++) {
                float p0 = ex2(s[n][j0]     - mn);
                float p1 = ex2(s[n][j0 + 1] - mn);
                ps += p0 + p1;
                const int slot = (n & 1) * 2 + half;
                pF[n >> 1][slot] = f16pack(p0, p1);
            }
            ps += __shfl_xor_sync(0xffffffffu, ps, 1);
            ps += __shfl_xor_sync(0xffffffffu, ps, 2);

            l_i[half] = l_i[half] * corr + ps;
            #pragma unroll
            for (int n = 0; n < 8; n++) {
                acc[n][j0]     *= corr;
                acc[n][j0 + 1] *= corr;
            }
        }

        #pragma unroll
        for (int kc = 0; kc < 4; kc++) {
            const unsigned ko = kc * 8 * 4;
            #pragma unroll
            for (int n2 = 0; n2 < 4; n2++) {
                const unsigned no = (unsigned)(n2 * 16 * VTP) * 4 + ko;
                unsigned v0, v1, v2, v3;
                ldsm4(v0, v1, v2, v3, aV + no);
                mma16h(acc[2*n2],   pF[kc][0], pF[kc][1], pF[kc][2], pF[kc][3], v0, v1);
                mma16h(acc[2*n2+1], pF[kc][0], pF[kc][1], pF[kc][2], pF[kc][3], v2, v3);
            }
        }
        __syncthreads();
    }

    float inv0 = 1.0f / l_i[0];
    float inv1 = 1.0f / l_i[1];
    float* Op = g_ao + ((size_t)b * SEQ + qb * BM) * VDIM + h * DV;
    #pragma unroll
    for (int n = 0; n < 8; n++) {
        float2 o0; o0.x = acc[n][0] * inv0; o0.y = acc[n][1] * inv0;
        float2 o1; o1.x = acc[n][2] * inv1; o1.y = acc[n][3] * inv1;
        *(float2*)&Op[(size_t)rA * VDIM + n * 8 + 2 * tg] = o0;
        *(float2*)&Op[(size_t)rB * VDIM + n * 8 + 2 * tg] = o1;
    }
}

// ---------------------------------------------------------------------------
// Kernel 3: output projection, N=128 per CTA (grid.y = 4).
// ---------------------------------------------------------------------------
#define OUT_SMEM ((2*128*AP + 2*128*WP) * 4)   // 40960 B

__global__ __launch_bounds__(256, 2) void out_mma(
    const float* __restrict__ Wo, float* __restrict__ out)
{
    extern __shared__ unsigned smo[];
    unsigned* Ah  = smo;
    unsigned* Al  = Ah  + 128 * AP;
    unsigned* Wth = Al  + 128 * AP;
    unsigned* Wtl = Wth + 128 * WP;

    const int b  = blockIdx.z;
    const int m0 = blockIdx.x * 128;
    const int n0 = blockIdx.y * 128;

    const float* A = g_ao + (size_t)b * SEQ * VDIM;
    float* C = out + (size_t)b * SEQ * CDIM;

    const int t    = threadIdx.x;
    const int w    = t >> 5;
    const int lane = t & 31;
    const int g    = lane >> 2;
    const int tg   = lane & 3;
    const int rA   = 16 * w + g;
    const int rB   = rA + 8;

    const unsigned aw = (unsigned)((16 * w + AROW(lane)) * AP + ACOL(lane)) * 4;
    const unsigned bw = (unsigned)(BROW(lane) * WP + BCOL(lane)) * 4;
    const unsigned aH = sptr(Ah) + aw,  aL = sptr(Al) + aw;
    const unsigned bH = sptr(Wth) + bw, bL = sptr(Wtl) + bw;

    float acc[16][4];
    #pragma unroll
    for (int n = 0; n < 16; n++)
        #pragma unroll
        for (int j = 0; j < 4; j++) acc[n][j] = 0.0f;

    for (int k0 = 0; k0 < VDIM; k0 += 32) {
        __syncthreads();
        #pragma unroll
        for (int i = t; i < 128 * 16; i += 256) {
            int m = i >> 4, kp = i & 15;
            float2 v2 = *(const float2*)&A[(size_t)(m0 + m) * VDIM + k0 + 2 * kp];
            unsigned hi, lo; bsplit(v2.x, v2.y, hi, lo);
            Ah[m * AP + kp] = hi; Al[m * AP + kp] = lo;
        }
        #pragma unroll
        for (int i = t; i < 128 * 16; i += 256) {
            int n = i & 127, kp = i >> 7;
            float v0 = Wo[(size_t)(k0 + 2 * kp)     * CDIM + n0 + n];
            float v1 = Wo[(size_t)(k0 + 2 * kp + 1) * CDIM + n0 + n];
            unsigned hi, lo; bsplit(v0, v1, hi, lo);
            Wth[n * WP + kp] = hi; Wtl[n * WP + kp] = lo;
        }
        __syncthreads();

        #pragma unroll
        for (int kc2 = 0; kc2 < 2; kc2++) {
            const unsigned ko = kc2 * 8 * 4;
            unsigned ah0, ah1, ah2, ah3, al0, al1, al2, al3;
            ldsm4(ah0, ah1, ah2, ah3, aH + ko);
            ldsm4(al0, al1, al2, al3, aL + ko);
            #pragma unroll
            for (int n2 = 0; n2 < 8; n2++) {
                const unsigned no = (unsigned)(n2 * 16 * WP) * 4 + ko;
                unsigned h0, h1, h2, h3, q0, q1, q2, q3;
                ldsm4(h0, h1, h2, h3, bH + no);
                ldsm4(q0, q1, q2, q3, bL + no);
                mma16(acc[2*n2],   ah0, ah1, ah2, ah3, h0, h1);
                mma16(acc[2*n2],   ah0, ah1, ah2, ah3, q0, q1);
                mma16(acc[2*n2],   al0, al1, al2, al3, h0, h1);
                mma16(acc[2*n2+1], ah0, ah1, ah2, ah3, h2, h3);
                mma16(acc[2*n2+1], ah0, ah1, ah2, ah3, q2, q3);
                mma16(acc[2*n2+1], al0, al1, al2, al3, h2, h3);
            }
        }
    }

    #pragma unroll
    for (int n = 0; n < 16; n++) {
        float2 o0, o1;
        o0.x = acc[n][0]; o0.y = acc[n][1];
        o1.x = acc[n][2]; o1.y = acc[n][3];
        *(float2*)&C[(size_t)(m0 + rA) * CDIM + n0 + n * 8 + 2 * tg] = o0;
        *(float2*)&C[(size_t)(m0 + rB) * CDIM + n0 + n * 8 + 2 * tg] = o1;
    }
}

extern "C" void kernel_launch(void* const* d_in, const int* in_sizes, int n_in,
                              void* d_out, int out_size)
{
    const float* X  = (const float*)d_in[0];
    const float* Wq = (const float*)d_in[1];
    const float* Wk = (const float*)d_in[2];
    const float* Wv = (const float*)d_in[3];
    const float* Wo = (const float*)d_in[4];
    float* out = (float*)d_out;

    cudaFuncSetAttribute(attn_kernel,
                         cudaFuncAttributeMaxDynamicSharedMemorySize, ATTN_SMEM);

    dim3 g1(SEQ / 128, 8, BATCH);
    qkv_mma<<<g1, 256, QKV_SMEM>>>(X, Wq, Wk, Wv);

    dim3 g2(SEQ / BM, NH, BATCH);
    attn_kernel<<<g2, 256, ATTN_SMEM>>>();

    dim3 g3(SEQ / 128, CDIM / 128, BATCH);
    out_mma<<<g3, 256, OUT_SMEM>>>(Wo, out);
}